// round 6
// baseline (speedup 1.0000x reference)
#include <cuda_runtime.h>
#include <cstdint>

// ============================================================================
// VocabularyAttention on GB300 (sm_103a), mma.sync m16n8k8 tf32 + cp.async.
// All GEMM operands are scratch copies that are (a) pre-rounded to tf32 and
// (b) stored with a within-8 K-permutation [0,4,1,5,2,6,3,7] so that every
// mma fragment pair is one aligned LDS.64.
//
//   1. xr = roundperm(x); wlr = roundperm(Wl); wvr = roundperm(Wv);
//      wvt = roundperm-transpose(Wv)  (pad V -> VPAD with zeros)
//   2. logits = xr @ wvr^T + bv            (perm stores; pad -> -1e30)
//   3. softmax rows in place (perm-equivariant), p = round(exp(x-m)/l)
//   4. hp[z] = p @ wvt^T  (split-K=8);  h = roundperm(sum hp)
//   5. out = h @ wlr^T + bl                (natural-order output)
// ============================================================================

#define VOCAB 50257
#define VPAD  50432      // 197*256
#define DDIM  768
#define MROWS 4096
#define SPLITK 8
#define KSPLIT (VPAD / SPLITK)   // 6304 = 197*32

__device__ float g_probs[(size_t)MROWS * VPAD];    // ~826 MB
__device__ float g_wvt[(size_t)DDIM * VPAD];       // rounded+perm, padded
__device__ float g_wvr[(size_t)VOCAB * DDIM];      // rounded+perm copy
__device__ float g_xr[(size_t)MROWS * DDIM];
__device__ float g_wlr[(size_t)DDIM * DDIM];
__device__ float g_hp[(size_t)SPLITK * MROWS * DDIM];
__device__ float g_h[(size_t)MROWS * DDIM];

// ---------------------------------------------------------------------------
__device__ __forceinline__ uint32_t smem_u32(const void* p) {
    uint32_t a;
    asm("{ .reg .u64 t; cvta.to.shared.u64 t, %1; cvt.u32.u64 %0, t; }"
        : "=r"(a) : "l"(p));
    return a;
}

__device__ __forceinline__ float tf32r(float f) {
    uint32_t r;
    asm("cvt.rna.tf32.f32 %0, %1;" : "=r"(r) : "f"(f));
    return __uint_as_float(r);
}

// position of logical k (0..7) in permuted order [0,4,1,5,2,6,3,7]
__device__ __forceinline__ int pos8(int k) { return ((k & 3) << 1) | (k >> 2); }

__device__ __forceinline__ void mma_tf32(float c[4],
                                         uint32_t a0, uint32_t a1,
                                         uint32_t a2, uint32_t a3,
                                         uint32_t b0, uint32_t b1) {
    asm volatile(
        "mma.sync.aligned.m16n8k8.row.col.f32.tf32.tf32.f32 "
        "{%0,%1,%2,%3}, {%4,%5,%6,%7}, {%8,%9}, {%0,%1,%2,%3};"
        : "+f"(c[0]), "+f"(c[1]), "+f"(c[2]), "+f"(c[3])
        : "r"(a0), "r"(a1), "r"(a2), "r"(a3), "r"(b0), "r"(b1));
}

// ============================================================================
// GEMM:  C[M,N] = A[M,K] @ B[N,K]^T   (K-axes pre-rounded + perm8)
// CTA tile 128x256, 16 warps (4m x 4n), warp tile 32x64, BK=32,
// 3-stage cp.async pipeline, LDS.64 fragment fetches.
// epi_mode: 0 = +aux[col], cols >= nvalidB -> -1e30, PERM column stores
//           2 = +aux[col], natural stores            (final bias)
//           3 = plain natural stores                 (split-K partials)
// ============================================================================
constexpr int BK      = 32;
constexpr int LDS_F   = 40;               // 8B-bank = 4g+t -> conflict-free
constexpr int A_STAGE = 128 * LDS_F;      // 5120 floats
constexpr int B_STAGE = 256 * LDS_F;      // 10240 floats
constexpr int NSTAGE  = 3;
constexpr int GEMM_SMEM = NSTAGE * (A_STAGE + B_STAGE) * 4;   // 184320 B

__global__ void __launch_bounds__(512, 1)
gemm_tn(const float* __restrict__ A, long long lda,
        const float* __restrict__ B, long long ldb,
        float* __restrict__ C, long long ldc, long long c_zstride,
        int Kps, int nvalidB,
        const float* __restrict__ aux, int epi_mode)
{
    extern __shared__ float sm[];
    float* sA = sm;                          // [3][128][40]
    float* sB = sm + NSTAGE * A_STAGE;       // [3][256][40]

    const int tid  = threadIdx.x;
    const int wid  = tid >> 5;       // 0..15
    const int lane = tid & 31;
    const int g    = lane >> 2;      // 0..7
    const int t    = lane & 3;       // 0..3
    const int wm   = wid >> 2;       // 0..3
    const int wn   = wid & 3;        // 0..3
    const int m0   = blockIdx.x * 128;
    const int n0   = blockIdx.y * 256;

    const long long koff = (long long)blockIdx.z * Kps;
    A += koff;
    B += koff;
    C += (long long)blockIdx.z * c_zstride;

    // ---- tile loader: 512 threads ----
    auto load_tiles = [&](int c, int s) {
        const float* Ab = A + (size_t)m0 * lda + (size_t)c * BK;
        const float* Bb = B + (size_t)c * BK;
        const uint32_t sAa = smem_u32(sA + s * A_STAGE);
        const uint32_t sBa = smem_u32(sB + s * B_STAGE);
        #pragma unroll
        for (int q = 0; q < 2; ++q) {                // A: 128 rows x 8 f4
            int idx = tid + q * 512;
            int r = idx >> 3, j = idx & 7;
            const float* gp = Ab + (size_t)r * lda + j * 4;
            uint32_t da = sAa + (uint32_t)(r * LDS_F + j * 4) * 4;
            asm volatile("cp.async.cg.shared.global [%0], [%1], 16;"
                         :: "r"(da), "l"(gp) : "memory");
        }
        #pragma unroll
        for (int q = 0; q < 4; ++q) {                // B: 256 rows x 8 f4
            int idx = tid + q * 512;
            int r = idx >> 3, j = idx & 7;
            int gn = n0 + r;
            int ok = (gn < nvalidB);
            const float* gq = Bb + (size_t)(ok ? gn : 0) * ldb + j * 4;
            uint32_t db = sBa + (uint32_t)(r * LDS_F + j * 4) * 4;
            int sz = ok ? 16 : 0;
            asm volatile("cp.async.cg.shared.global [%0], [%1], 16, %2;"
                         :: "r"(db), "l"(gq), "r"(sz) : "memory");
        }
        asm volatile("cp.async.commit_group;" ::: "memory");
    };

    float acc[2][8][4];
    #pragma unroll
    for (int i = 0; i < 2; ++i)
        #pragma unroll
        for (int j = 0; j < 8; ++j)
            #pragma unroll
            for (int k = 0; k < 4; ++k) acc[i][j][k] = 0.f;

    const int NCH = Kps / BK;
    load_tiles(0, 0);
    if (NCH > 1) load_tiles(1, 1);

    for (int c = 0; c < NCH; ++c) {
        if (c + 1 < NCH) {
            asm volatile("cp.async.wait_group 1;" ::: "memory");
        } else {
            asm volatile("cp.async.wait_group 0;" ::: "memory");
        }
        __syncthreads();
        if (c + 2 < NCH) load_tiles(c + 2, (c + 2) % NSTAGE);

        const int s = c % NSTAGE;
        const uint32_t* tA = reinterpret_cast<const uint32_t*>(sA + s * A_STAGE);
        const uint32_t* tB = reinterpret_cast<const uint32_t*>(sB + s * B_STAGE);

        #pragma unroll
        for (int ks = 0; ks < 4; ++ks) {
            const int kb = ks * 8 + 2 * t;          // permuted pair offset
            uint2 bf[8];
            #pragma unroll
            for (int ni = 0; ni < 8; ++ni) {
                int col = wn * 64 + ni * 8 + g;
                bf[ni] = *reinterpret_cast<const uint2*>(tB + col * LDS_F + kb);
            }
            #pragma unroll
            for (int mi = 0; mi < 2; ++mi) {
                int rr = wm * 32 + mi * 16 + g;
                // qa = {a0 (k=t), a2 (k=t+4)} ; qb = {a1, a3} (row rr+8)
                uint2 qa = *reinterpret_cast<const uint2*>(tA + rr * LDS_F + kb);
                uint2 qb = *reinterpret_cast<const uint2*>(tA + (rr + 8) * LDS_F + kb);
                #pragma unroll
                for (int ni = 0; ni < 8; ++ni)
                    mma_tf32(acc[mi][ni], qa.x, qb.x, qa.y, qb.y,
                             bf[ni].x, bf[ni].y);
            }
        }
        __syncthreads();
    }

    // ---- epilogue ----
    const int c8a = 2 * t;                 // logical col offsets within 8-group
    const int p0 = pos8(c8a);              // permuted positions (mode 0)
    const int p1 = pos8(c8a + 1);
    #pragma unroll
    for (int mi = 0; mi < 2; ++mi) {
        const int rr = m0 + wm * 32 + mi * 16 + g;
        #pragma unroll
        for (int ni = 0; ni < 8; ++ni) {
            const int base = n0 + wn * 64 + ni * 8;   // 8-group base (logical)
            const int col  = base + c8a;
            float v0 = acc[mi][ni][0], v1 = acc[mi][ni][1];
            float v2 = acc[mi][ni][2], v3 = acc[mi][ni][3];
            if (epi_mode == 0) {
                float b0 = (col     < nvalidB) ? aux[col]     : 0.f;
                float b1 = (col + 1 < nvalidB) ? aux[col + 1] : 0.f;
                v0 += b0; v1 += b1; v2 += b0; v3 += b1;
                if (col     >= nvalidB) { v0 = -1e30f; v2 = -1e30f; }
                if (col + 1 >= nvalidB) { v1 = -1e30f; v3 = -1e30f; }
                C[(size_t)rr * ldc + base + p0]       = v0;
                C[(size_t)rr * ldc + base + p1]       = v1;
                C[(size_t)(rr + 8) * ldc + base + p0] = v2;
                C[(size_t)(rr + 8) * ldc + base + p1] = v3;
            } else {
                if (epi_mode == 2) {
                    float b0 = aux[col], b1 = aux[col + 1];
                    v0 += b0; v1 += b1; v2 += b0; v3 += b1;
                }
                *reinterpret_cast<float2*>(C + (size_t)rr * ldc + col) =
                    make_float2(v0, v1);
                *reinterpret_cast<float2*>(C + (size_t)(rr + 8) * ldc + col) =
                    make_float2(v2, v3);
            }
        }
    }
}

// ============================================================================
// prep: rounded + perm8 copy. Each thread handles 8 consecutive floats.
// ============================================================================
__global__ void __launch_bounds__(256)
round_copy_perm(const float* __restrict__ in, float* __restrict__ out,
                long long n)
{
    long long i8 = ((long long)blockIdx.x * 256 + threadIdx.x) * 8;
    if (i8 >= n) return;
    float4 u = *reinterpret_cast<const float4*>(in + i8);
    float4 v = *reinterpret_cast<const float4*>(in + i8 + 4);
    float4 o0 = make_float4(tf32r(u.x), tf32r(v.x), tf32r(u.y), tf32r(v.y));
    float4 o1 = make_float4(tf32r(u.z), tf32r(v.z), tf32r(u.w), tf32r(v.w));
    *reinterpret_cast<float4*>(out + i8)     = o0;
    *reinterpret_cast<float4*>(out + i8 + 4) = o1;
}

// ============================================================================
// WvT[d, perm(v)] = round(Wv[v, d])  (padded to VPAD with zeros)
// ============================================================================
__global__ void __launch_bounds__(256)
transpose_wv(const float* __restrict__ Wv, float* __restrict__ WvT)
{
    __shared__ float tt[32][33];
    const int v0 = blockIdx.x * 32;
    const int d0 = blockIdx.y * 32;
    const int tx = threadIdx.x & 31;
    const int ty = threadIdx.x >> 5;     // 0..7
    #pragma unroll
    for (int i = 0; i < 32; i += 8) {
        int v = v0 + ty + i;
        tt[ty + i][tx] = (v < VOCAB) ? tf32r(Wv[(size_t)v * DDIM + d0 + tx]) : 0.f;
    }
    __syncthreads();
    const int pcol = v0 + (tx & 24) + pos8(tx & 7);
    #pragma unroll
    for (int i = 0; i < 32; i += 8)
        WvT[(size_t)(d0 + ty + i) * VPAD + pcol] = tt[tx][ty + i];
}

// ============================================================================
// Row softmax (perm-equivariant): online (m,l), p = round(exp(x-m)/l).
// ============================================================================
__global__ void __launch_bounds__(256)
softmax_rows(float* __restrict__ L)
{
    __shared__ float sm_m[256], sm_s[256];
    const int row = blockIdx.x;
    float* rp = L + (size_t)row * VPAD;
    const int tid = threadIdx.x;

    float m = -3.0e38f, s = 0.f;
    for (int i = tid; i < VPAD / 4; i += 256) {
        float4 v = reinterpret_cast<const float4*>(rp)[i];
        float xs[4] = {v.x, v.y, v.z, v.w};
        #pragma unroll
        for (int q = 0; q < 4; ++q) {
            float x = xs[q];
            if (x > m) { s = s * __expf(m - x) + 1.f; m = x; }
            else       { s += __expf(x - m); }
        }
    }
    sm_m[tid] = m; sm_s[tid] = s;
    __syncthreads();
    for (int off = 128; off > 0; off >>= 1) {
        if (tid < off) {
            float m2 = sm_m[tid + off], s2 = sm_s[tid + off];
            float m1 = sm_m[tid],       s1 = sm_s[tid];
            float M = fmaxf(m1, m2);
            sm_s[tid] = s1 * __expf(m1 - M) + s2 * __expf(m2 - M);
            sm_m[tid] = M;
        }
        __syncthreads();
    }
    const float M = sm_m[0];
    const float R = 1.0f / sm_s[0];

    for (int i = tid; i < VPAD / 4; i += 256) {
        float4 v = reinterpret_cast<const float4*>(rp)[i];
        v.x = tf32r(__expf(v.x - M) * R);
        v.y = tf32r(__expf(v.y - M) * R);
        v.z = tf32r(__expf(v.z - M) * R);
        v.w = tf32r(__expf(v.w - M) * R);
        reinterpret_cast<float4*>(rp)[i] = v;
    }
}

// ============================================================================
// split-K reduction: h = roundperm(sum_z hp[z])   (8 floats per thread)
// ============================================================================
__global__ void __launch_bounds__(256)
reduce_splitk(const float* __restrict__ hp, float* __restrict__ h)
{
    const size_t MD = (size_t)MROWS * DDIM;
    size_t i8 = ((size_t)blockIdx.x * 256 + threadIdx.x) * 8;
    float4 u = *reinterpret_cast<const float4*>(hp + i8);
    float4 v = *reinterpret_cast<const float4*>(hp + i8 + 4);
    #pragma unroll
    for (int z = 1; z < SPLITK; ++z) {
        float4 bu = *reinterpret_cast<const float4*>(hp + z * MD + i8);
        float4 bv = *reinterpret_cast<const float4*>(hp + z * MD + i8 + 4);
        u.x += bu.x; u.y += bu.y; u.z += bu.z; u.w += bu.w;
        v.x += bv.x; v.y += bv.y; v.z += bv.z; v.w += bv.w;
    }
    float4 o0 = make_float4(tf32r(u.x), tf32r(v.x), tf32r(u.y), tf32r(v.y));
    float4 o1 = make_float4(tf32r(u.z), tf32r(v.z), tf32r(u.w), tf32r(v.w));
    *reinterpret_cast<float4*>(h + i8)     = o0;
    *reinterpret_cast<float4*>(h + i8 + 4) = o1;
}

// ============================================================================
// host launcher
// ============================================================================
extern "C" void kernel_launch(void* const* d_in, const int* in_sizes, int n_in,
                              void* d_out, int out_size)
{
    const float* x  = (const float*)d_in[0];
    const float* Wv = (const float*)d_in[1];
    const float* bv = (const float*)d_in[2];
    const float* Wl = (const float*)d_in[3];
    const float* bl = (const float*)d_in[4];
    float* out = (float*)d_out;

    void *p_probs, *p_wvt, *p_wvr, *p_xr, *p_wlr, *p_hp, *p_h;
    cudaGetSymbolAddress(&p_probs, g_probs);
    cudaGetSymbolAddress(&p_wvt,   g_wvt);
    cudaGetSymbolAddress(&p_wvr,   g_wvr);
    cudaGetSymbolAddress(&p_xr,    g_xr);
    cudaGetSymbolAddress(&p_wlr,   g_wlr);
    cudaGetSymbolAddress(&p_hp,    g_hp);
    cudaGetSymbolAddress(&p_h,     g_h);
    float* probs = (float*)p_probs;
    float* wvt   = (float*)p_wvt;
    float* wvr   = (float*)p_wvr;
    float* xr    = (float*)p_xr;
    float* wlr   = (float*)p_wlr;
    float* hp    = (float*)p_hp;
    float* h     = (float*)p_h;

    static bool attr_set = false;
    if (!attr_set) {
        cudaFuncSetAttribute(gemm_tn,
            cudaFuncAttributeMaxDynamicSharedMemorySize, GEMM_SMEM);
        attr_set = true;
    }

    // 1) prep: rounded + perm8 copies of x, Wl, Wv; perm transpose of Wv
    const long long nX = (long long)MROWS * DDIM;
    const long long nL = (long long)DDIM * DDIM;
    const long long nV = (long long)VOCAB * DDIM;
    round_copy_perm<<<(int)((nX / 8 + 255) / 256), 256>>>(x, xr, nX);
    round_copy_perm<<<(int)((nL / 8 + 255) / 256), 256>>>(Wl, wlr, nL);
    round_copy_perm<<<(int)((nV / 8 + 255) / 256), 256>>>(Wv, wvr, nV);
    transpose_wv<<<dim3(VPAD / 32, DDIM / 32), 256>>>(Wv, wvt);

    // 2) logits = xr @ wvr^T + bv  (perm column stores)
    gemm_tn<<<dim3(MROWS / 128, VPAD / 256, 1), 512, GEMM_SMEM>>>(
        xr, DDIM, wvr, DDIM, probs, VPAD, 0, DDIM, VOCAB, bv, 0);

    // 3) softmax in place
    softmax_rows<<<MROWS, 256>>>(probs);

    // 4) hp[z] = p @ wvt^T (split-K), then h = roundperm(sum)
    gemm_tn<<<dim3(MROWS / 128, DDIM / 256, SPLITK), 512, GEMM_SMEM>>>(
        probs, VPAD, wvt, VPAD, hp, DDIM, (long long)MROWS * DDIM,
        KSPLIT, DDIM, nullptr, 3);
    reduce_splitk<<<MROWS * DDIM / 2048, 256>>>(hp, h);

    // 5) out = h @ wlr^T + bl
    gemm_tn<<<dim3(MROWS / 128, DDIM / 256, 1), 512, GEMM_SMEM>>>(
        h, DDIM, wlr, DDIM, out, DDIM, 0, DDIM, DDIM, bl, 2);
}

// round 7
// speedup vs baseline: 1.0854x; 1.0854x over previous
#include <cuda_runtime.h>
#include <cstdint>

// ============================================================================
// VocabularyAttention on GB300 (sm_103a), mma.sync m16n8k8 tf32 + cp.async.
// R4 warp geometry (8 warps, 64x64 warp tile) + perm8 K-layout so every mma
// fragment pair is one aligned LDS.64. All GEMM operands are pre-rounded
// tf32 scratch copies stored with within-8 K-permutation [0,4,1,5,2,6,3,7].
//
//   1. xr = roundperm(x); wlr = roundperm(Wl); wvr = roundperm(Wv);
//      wvt = roundperm-transpose(Wv)  (pad V -> VPAD with zeros)
//   2. logits = xr @ wvr^T + bv            (perm stores; pad -> -1e30)
//   3. softmax rows in place (perm-equivariant), p = round(exp(x-m)/l)
//   4. hp[z] = p @ wvt^T  (split-K=4);  h = roundperm(sum hp)
//   5. out = h @ wlr^T + bl                (natural-order output)
// ============================================================================

#define VOCAB 50257
#define VPAD  50432      // 197*256
#define DDIM  768
#define MROWS 4096
#define SPLITK 4
#define KSPLIT (VPAD / SPLITK)   // 12608 = 394*32

__device__ float g_probs[(size_t)MROWS * VPAD];    // ~826 MB
__device__ float g_wvt[(size_t)DDIM * VPAD];       // rounded+perm, padded
__device__ float g_wvr[(size_t)VOCAB * DDIM];      // rounded+perm copy
__device__ float g_xr[(size_t)MROWS * DDIM];
__device__ float g_wlr[(size_t)DDIM * DDIM];
__device__ float g_hp[(size_t)SPLITK * MROWS * DDIM];
__device__ float g_h[(size_t)MROWS * DDIM];

// ---------------------------------------------------------------------------
__device__ __forceinline__ uint32_t smem_u32(const void* p) {
    uint32_t a;
    asm("{ .reg .u64 t; cvta.to.shared.u64 t, %1; cvt.u32.u64 %0, t; }"
        : "=r"(a) : "l"(p));
    return a;
}

__device__ __forceinline__ float tf32r(float f) {
    uint32_t r;
    asm("cvt.rna.tf32.f32 %0, %1;" : "=r"(r) : "f"(f));
    return __uint_as_float(r);
}

// position of logical k (0..7) in permuted order [0,4,1,5,2,6,3,7]
__device__ __forceinline__ int pos8(int k) { return ((k & 3) << 1) | (k >> 2); }

__device__ __forceinline__ void mma_tf32(float c[4],
                                         uint32_t a0, uint32_t a1,
                                         uint32_t a2, uint32_t a3,
                                         uint32_t b0, uint32_t b1) {
    asm volatile(
        "mma.sync.aligned.m16n8k8.row.col.f32.tf32.tf32.f32 "
        "{%0,%1,%2,%3}, {%4,%5,%6,%7}, {%8,%9}, {%0,%1,%2,%3};"
        : "+f"(c[0]), "+f"(c[1]), "+f"(c[2]), "+f"(c[3])
        : "r"(a0), "r"(a1), "r"(a2), "r"(a3), "r"(b0), "r"(b1));
}

// ============================================================================
// GEMM:  C[M,N] = A[M,K] @ B[N,K]^T   (K-axes pre-rounded + perm8)
// CTA tile 128x256, 8 warps (2m x 4n), warp tile 64x64, BK=32,
// 3-stage cp.async pipeline, LDS.64 fragment fetches.
// epi_mode: 0 = +aux[col], cols >= nvalidB -> -1e30, PERM column stores
//           2 = +aux[col], natural stores            (final bias)
//           3 = plain natural stores                 (split-K partials)
// ============================================================================
constexpr int BK      = 32;
constexpr int LDS_F   = 40;               // 8B-bank = 4g+t -> conflict-free
constexpr int A_STAGE = 128 * LDS_F;      // 5120 floats
constexpr int B_STAGE = 256 * LDS_F;      // 10240 floats
constexpr int NSTAGE  = 3;
constexpr int GEMM_SMEM = NSTAGE * (A_STAGE + B_STAGE) * 4;   // 184320 B

__global__ void __launch_bounds__(256, 1)
gemm_tn(const float* __restrict__ A, long long lda,
        const float* __restrict__ B, long long ldb,
        float* __restrict__ C, long long ldc, long long c_zstride,
        int Kps, int nvalidB,
        const float* __restrict__ aux, int epi_mode)
{
    extern __shared__ float sm[];
    float* sA = sm;                          // [3][128][40]
    float* sB = sm + NSTAGE * A_STAGE;       // [3][256][40]

    const int tid  = threadIdx.x;
    const int wid  = tid >> 5;       // 0..7
    const int lane = tid & 31;
    const int g    = lane >> 2;      // 0..7
    const int t    = lane & 3;       // 0..3
    const int wm   = wid >> 2;       // 0..1
    const int wn   = wid & 3;        // 0..3
    const int m0   = blockIdx.x * 128;
    const int n0   = blockIdx.y * 256;

    const long long koff = (long long)blockIdx.z * Kps;
    A += koff;
    B += koff;
    C += (long long)blockIdx.z * c_zstride;

    // ---- tile loader: 256 threads ----
    auto load_tiles = [&](int c, int s) {
        const float* Ab = A + (size_t)m0 * lda + (size_t)c * BK;
        const float* Bb = B + (size_t)c * BK;
        const uint32_t sAa = smem_u32(sA + s * A_STAGE);
        const uint32_t sBa = smem_u32(sB + s * B_STAGE);
        #pragma unroll
        for (int q = 0; q < 4; ++q) {                // A: 128 rows x 8 f4
            int idx = tid + q * 256;
            int r = idx >> 3, j = idx & 7;
            const float* gp = Ab + (size_t)r * lda + j * 4;
            uint32_t da = sAa + (uint32_t)(r * LDS_F + j * 4) * 4;
            asm volatile("cp.async.cg.shared.global [%0], [%1], 16;"
                         :: "r"(da), "l"(gp) : "memory");
        }
        #pragma unroll
        for (int q = 0; q < 8; ++q) {                // B: 256 rows x 8 f4
            int idx = tid + q * 256;
            int r = idx >> 3, j = idx & 7;
            int gn = n0 + r;
            int ok = (gn < nvalidB);
            const float* gq = Bb + (size_t)(ok ? gn : 0) * ldb + j * 4;
            uint32_t db = sBa + (uint32_t)(r * LDS_F + j * 4) * 4;
            int sz = ok ? 16 : 0;
            asm volatile("cp.async.cg.shared.global [%0], [%1], 16, %2;"
                         :: "r"(db), "l"(gq), "r"(sz) : "memory");
        }
        asm volatile("cp.async.commit_group;" ::: "memory");
    };

    float acc[4][8][4];
    #pragma unroll
    for (int i = 0; i < 4; ++i)
        #pragma unroll
        for (int j = 0; j < 8; ++j)
            #pragma unroll
            for (int k = 0; k < 4; ++k) acc[i][j][k] = 0.f;

    const int NCH = Kps / BK;
    load_tiles(0, 0);
    if (NCH > 1) load_tiles(1, 1);

    for (int c = 0; c < NCH; ++c) {
        if (c + 1 < NCH) {
            asm volatile("cp.async.wait_group 1;" ::: "memory");
        } else {
            asm volatile("cp.async.wait_group 0;" ::: "memory");
        }
        __syncthreads();
        if (c + 2 < NCH) load_tiles(c + 2, (c + 2) % NSTAGE);

        const int s = c % NSTAGE;
        const uint32_t* tA = reinterpret_cast<const uint32_t*>(sA + s * A_STAGE);
        const uint32_t* tB = reinterpret_cast<const uint32_t*>(sB + s * B_STAGE);

        #pragma unroll
        for (int ks = 0; ks < 4; ++ks) {
            const int kb = ks * 8 + 2 * t;          // permuted pair offset
            uint2 bf[8];
            #pragma unroll
            for (int ni = 0; ni < 8; ++ni) {
                int col = wn * 64 + ni * 8 + g;
                bf[ni] = *reinterpret_cast<const uint2*>(tB + col * LDS_F + kb);
            }
            #pragma unroll
            for (int mi = 0; mi < 4; ++mi) {
                int rr = wm * 64 + mi * 16 + g;
                // qa = {a0 (k=t), a2 (k=t+4)} ; qb = {a1, a3} (row rr+8)
                uint2 qa = *reinterpret_cast<const uint2*>(tA + rr * LDS_F + kb);
                uint2 qb = *reinterpret_cast<const uint2*>(tA + (rr + 8) * LDS_F + kb);
                #pragma unroll
                for (int ni = 0; ni < 8; ++ni)
                    mma_tf32(acc[mi][ni], qa.x, qb.x, qa.y, qb.y,
                             bf[ni].x, bf[ni].y);
            }
        }
        __syncthreads();
    }

    // ---- epilogue ----
    const int c8a = 2 * t;                 // logical col offsets within 8-group
    const int p0 = pos8(c8a);              // permuted positions (mode 0)
    const int p1 = pos8(c8a + 1);
    #pragma unroll
    for (int mi = 0; mi < 4; ++mi) {
        const int rr = m0 + wm * 64 + mi * 16 + g;
        #pragma unroll
        for (int ni = 0; ni < 8; ++ni) {
            const int base = n0 + wn * 64 + ni * 8;   // 8-group base (logical)
            const int col  = base + c8a;
            float v0 = acc[mi][ni][0], v1 = acc[mi][ni][1];
            float v2 = acc[mi][ni][2], v3 = acc[mi][ni][3];
            if (epi_mode == 0) {
                float b0 = (col     < nvalidB) ? aux[col]     : 0.f;
                float b1 = (col + 1 < nvalidB) ? aux[col + 1] : 0.f;
                v0 += b0; v1 += b1; v2 += b0; v3 += b1;
                if (col     >= nvalidB) { v0 = -1e30f; v2 = -1e30f; }
                if (col + 1 >= nvalidB) { v1 = -1e30f; v3 = -1e30f; }
                C[(size_t)rr * ldc + base + p0]       = v0;
                C[(size_t)rr * ldc + base + p1]       = v1;
                C[(size_t)(rr + 8) * ldc + base + p0] = v2;
                C[(size_t)(rr + 8) * ldc + base + p1] = v3;
            } else {
                if (epi_mode == 2) {
                    float b0 = aux[col], b1 = aux[col + 1];
                    v0 += b0; v1 += b1; v2 += b0; v3 += b1;
                }
                *reinterpret_cast<float2*>(C + (size_t)rr * ldc + col) =
                    make_float2(v0, v1);
                *reinterpret_cast<float2*>(C + (size_t)(rr + 8) * ldc + col) =
                    make_float2(v2, v3);
            }
        }
    }
}

// ============================================================================
// prep: rounded + perm8 copy. Each thread handles 8 consecutive floats.
// ============================================================================
__global__ void __launch_bounds__(256)
round_copy_perm(const float* __restrict__ in, float* __restrict__ out,
                long long n)
{
    long long i8 = ((long long)blockIdx.x * 256 + threadIdx.x) * 8;
    if (i8 >= n) return;
    float4 u = *reinterpret_cast<const float4*>(in + i8);
    float4 v = *reinterpret_cast<const float4*>(in + i8 + 4);
    float4 o0 = make_float4(tf32r(u.x), tf32r(v.x), tf32r(u.y), tf32r(v.y));
    float4 o1 = make_float4(tf32r(u.z), tf32r(v.z), tf32r(u.w), tf32r(v.w));
    *reinterpret_cast<float4*>(out + i8)     = o0;
    *reinterpret_cast<float4*>(out + i8 + 4) = o1;
}

// ============================================================================
// WvT[d, perm(v)] = round(Wv[v, d])  (padded to VPAD with zeros)
// ============================================================================
__global__ void __launch_bounds__(256)
transpose_wv(const float* __restrict__ Wv, float* __restrict__ WvT)
{
    __shared__ float tt[32][33];
    const int v0 = blockIdx.x * 32;
    const int d0 = blockIdx.y * 32;
    const int tx = threadIdx.x & 31;
    const int ty = threadIdx.x >> 5;     // 0..7
    #pragma unroll
    for (int i = 0; i < 32; i += 8) {
        int v = v0 + ty + i;
        tt[ty + i][tx] = (v < VOCAB) ? tf32r(Wv[(size_t)v * DDIM + d0 + tx]) : 0.f;
    }
    __syncthreads();
    const int pcol = v0 + (tx & 24) + pos8(tx & 7);
    #pragma unroll
    for (int i = 0; i < 32; i += 8)
        WvT[(size_t)(d0 + ty + i) * VPAD + pcol] = tt[tx][ty + i];
}

// ============================================================================
// Row softmax (perm-equivariant): online (m,l), p = round(exp(x-m)/l).
// ============================================================================
__global__ void __launch_bounds__(256)
softmax_rows(float* __restrict__ L)
{
    __shared__ float sm_m[256], sm_s[256];
    const int row = blockIdx.x;
    float* rp = L + (size_t)row * VPAD;
    const int tid = threadIdx.x;

    float m = -3.0e38f, s = 0.f;
    for (int i = tid; i < VPAD / 4; i += 256) {
        float4 v = reinterpret_cast<const float4*>(rp)[i];
        float xs[4] = {v.x, v.y, v.z, v.w};
        #pragma unroll
        for (int q = 0; q < 4; ++q) {
            float x = xs[q];
            if (x > m) { s = s * __expf(m - x) + 1.f; m = x; }
            else       { s += __expf(x - m); }
        }
    }
    sm_m[tid] = m; sm_s[tid] = s;
    __syncthreads();
    for (int off = 128; off > 0; off >>= 1) {
        if (tid < off) {
            float m2 = sm_m[tid + off], s2 = sm_s[tid + off];
            float m1 = sm_m[tid],       s1 = sm_s[tid];
            float M = fmaxf(m1, m2);
            sm_s[tid] = s1 * __expf(m1 - M) + s2 * __expf(m2 - M);
            sm_m[tid] = M;
        }
        __syncthreads();
    }
    const float M = sm_m[0];
    const float R = 1.0f / sm_s[0];

    for (int i = tid; i < VPAD / 4; i += 256) {
        float4 v = reinterpret_cast<const float4*>(rp)[i];
        v.x = tf32r(__expf(v.x - M) * R);
        v.y = tf32r(__expf(v.y - M) * R);
        v.z = tf32r(__expf(v.z - M) * R);
        v.w = tf32r(__expf(v.w - M) * R);
        reinterpret_cast<float4*>(rp)[i] = v;
    }
}

// ============================================================================
// split-K reduction: h = roundperm(sum_z hp[z])   (8 floats per thread)
// ============================================================================
__global__ void __launch_bounds__(256)
reduce_splitk(const float* __restrict__ hp, float* __restrict__ h)
{
    const size_t MD = (size_t)MROWS * DDIM;
    size_t i8 = ((size_t)blockIdx.x * 256 + threadIdx.x) * 8;
    float4 u = *reinterpret_cast<const float4*>(hp + i8);
    float4 v = *reinterpret_cast<const float4*>(hp + i8 + 4);
    #pragma unroll
    for (int z = 1; z < SPLITK; ++z) {
        float4 bu = *reinterpret_cast<const float4*>(hp + z * MD + i8);
        float4 bv = *reinterpret_cast<const float4*>(hp + z * MD + i8 + 4);
        u.x += bu.x; u.y += bu.y; u.z += bu.z; u.w += bu.w;
        v.x += bv.x; v.y += bv.y; v.z += bv.z; v.w += bv.w;
    }
    float4 o0 = make_float4(tf32r(u.x), tf32r(v.x), tf32r(u.y), tf32r(v.y));
    float4 o1 = make_float4(tf32r(u.z), tf32r(v.z), tf32r(u.w), tf32r(v.w));
    *reinterpret_cast<float4*>(h + i8)     = o0;
    *reinterpret_cast<float4*>(h + i8 + 4) = o1;
}

// ============================================================================
// host launcher
// ============================================================================
extern "C" void kernel_launch(void* const* d_in, const int* in_sizes, int n_in,
                              void* d_out, int out_size)
{
    const float* x  = (const float*)d_in[0];
    const float* Wv = (const float*)d_in[1];
    const float* bv = (const float*)d_in[2];
    const float* Wl = (const float*)d_in[3];
    const float* bl = (const float*)d_in[4];
    float* out = (float*)d_out;

    void *p_probs, *p_wvt, *p_wvr, *p_xr, *p_wlr, *p_hp, *p_h;
    cudaGetSymbolAddress(&p_probs, g_probs);
    cudaGetSymbolAddress(&p_wvt,   g_wvt);
    cudaGetSymbolAddress(&p_wvr,   g_wvr);
    cudaGetSymbolAddress(&p_xr,    g_xr);
    cudaGetSymbolAddress(&p_wlr,   g_wlr);
    cudaGetSymbolAddress(&p_hp,    g_hp);
    cudaGetSymbolAddress(&p_h,     g_h);
    float* probs = (float*)p_probs;
    float* wvt   = (float*)p_wvt;
    float* wvr   = (float*)p_wvr;
    float* xr    = (float*)p_xr;
    float* wlr   = (float*)p_wlr;
    float* hp    = (float*)p_hp;
    float* h     = (float*)p_h;

    static bool attr_set = false;
    if (!attr_set) {
        cudaFuncSetAttribute(gemm_tn,
            cudaFuncAttributeMaxDynamicSharedMemorySize, GEMM_SMEM);
        attr_set = true;
    }

    // 1) prep: rounded + perm8 copies of x, Wl, Wv; perm transpose of Wv
    const long long nX = (long long)MROWS * DDIM;
    const long long nL = (long long)DDIM * DDIM;
    const long long nV = (long long)VOCAB * DDIM;
    round_copy_perm<<<(int)((nX / 8 + 255) / 256), 256>>>(x, xr, nX);
    round_copy_perm<<<(int)((nL / 8 + 255) / 256), 256>>>(Wl, wlr, nL);
    round_copy_perm<<<(int)((nV / 8 + 255) / 256), 256>>>(Wv, wvr, nV);
    transpose_wv<<<dim3(VPAD / 32, DDIM / 32), 256>>>(Wv, wvt);

    // 2) logits = xr @ wvr^T + bv  (perm column stores)
    gemm_tn<<<dim3(MROWS / 128, VPAD / 256, 1), 256, GEMM_SMEM>>>(
        xr, DDIM, wvr, DDIM, probs, VPAD, 0, DDIM, VOCAB, bv, 0);

    // 3) softmax in place
    softmax_rows<<<MROWS, 256>>>(probs);

    // 4) hp[z] = p @ wvt^T (split-K), then h = roundperm(sum)
    gemm_tn<<<dim3(MROWS / 128, DDIM / 256, SPLITK), 256, GEMM_SMEM>>>(
        probs, VPAD, wvt, VPAD, hp, DDIM, (long long)MROWS * DDIM,
        KSPLIT, DDIM, nullptr, 3);
    reduce_splitk<<<MROWS * DDIM / 2048, 256>>>(hp, h);

    // 5) out = h @ wlr^T + bl
    gemm_tn<<<dim3(MROWS / 128, DDIM / 256, 1), 256, GEMM_SMEM>>>(
        h, DDIM, wlr, DDIM, out, DDIM, 0, DDIM, DDIM, bl, 2);
}

// round 8
// speedup vs baseline: 1.1709x; 1.0788x over previous
#include <cuda_runtime.h>
#include <cstdint>

// ============================================================================
// VocabularyAttention on GB300 (sm_103a), mma.sync m16n8k8 tf32 + cp.async.
// BK=64 / 2-stage pipeline. GEMM operand layouts:
//   - GEMM1: A=xr (perm8 K), B=wvr (perm8 K)        -> all LDS.64 fragments
//   - GEMM2: A=probs (natural), B=wvt (perm8 vocab) -> A via LDS.32 pairs
//   - GEMM3: A=h (natural),    B=wlr (perm8 K)
// perm8 = within-8 K-permutation [0,4,1,5,2,6,3,7] making each mma fragment
// pair one aligned LDS.64. probs/h natural => coalesced epilogue stores.
// ============================================================================

#define VOCAB 50257
#define VPAD  50432      // 197*256, divisible by 64
#define DDIM  768
#define MROWS 4096
#define SPLITK 4
#define KSPLIT (VPAD / SPLITK)   // 12608 = 197*64

__device__ float g_probs[(size_t)MROWS * VPAD];    // ~826 MB
__device__ float g_wvt[(size_t)DDIM * VPAD];       // rounded, vocab perm8
__device__ float g_wvr[(size_t)VOCAB * DDIM];      // rounded, K perm8
__device__ float g_xr[(size_t)MROWS * DDIM];       // rounded, K perm8
__device__ float g_wlr[(size_t)DDIM * DDIM];       // rounded, K perm8
__device__ float g_hp[(size_t)SPLITK * MROWS * DDIM];
__device__ float g_h[(size_t)MROWS * DDIM];        // natural

// ---------------------------------------------------------------------------
__device__ __forceinline__ uint32_t smem_u32(const void* p) {
    uint32_t a;
    asm("{ .reg .u64 t; cvta.to.shared.u64 t, %1; cvt.u32.u64 %0, t; }"
        : "=r"(a) : "l"(p));
    return a;
}

__device__ __forceinline__ float tf32r(float f) {
    uint32_t r;
    asm("cvt.rna.tf32.f32 %0, %1;" : "=r"(r) : "f"(f));
    return __uint_as_float(r);
}

// position of logical k (0..7) in permuted order [0,4,1,5,2,6,3,7]
__device__ __forceinline__ int pos8(int k) { return ((k & 3) << 1) | (k >> 2); }

__device__ __forceinline__ void mma_tf32(float c[4],
                                         uint32_t a0, uint32_t a1,
                                         uint32_t a2, uint32_t a3,
                                         uint32_t b0, uint32_t b1) {
    asm volatile(
        "mma.sync.aligned.m16n8k8.row.col.f32.tf32.tf32.f32 "
        "{%0,%1,%2,%3}, {%4,%5,%6,%7}, {%8,%9}, {%0,%1,%2,%3};"
        : "+f"(c[0]), "+f"(c[1]), "+f"(c[2]), "+f"(c[3])
        : "r"(a0), "r"(a1), "r"(a2), "r"(a3), "r"(b0), "r"(b1));
}

// ============================================================================
// GEMM:  C[M,N] = A[M,K] @ B[N,K]^T
// CTA tile 128x256, 8 warps (2m x 4n), warp tile 64x64, BK=64, 2 stages.
// APERM: A K-layout perm8 (LDS.64 frags) vs natural (LDS.32 pairs).
// epi_mode: 0 = +aux[col], cols >= nvalidB -> -1e30  (logits, natural store)
//           2 = +aux[col]                            (final bias)
//           3 = plain store                          (split-K partials)
// ============================================================================
constexpr int BK = 64;

template<bool APERM>
__global__ void __launch_bounds__(256, 1)
gemm_tn(const float* __restrict__ A, long long lda,
        const float* __restrict__ B, long long ldb,
        float* __restrict__ C, long long ldc, long long c_zstride,
        int Kps, int nvalidB,
        const float* __restrict__ aux, int epi_mode)
{
    constexpr int AS = APERM ? 72 : 68;   // floats/row: 72->8 mod 32 (LDS.64
    constexpr int BS = 72;                // half-warp CF), 68->4 mod 32 (LDS.32 CF)
    constexpr int A_STAGE = 128 * AS;
    constexpr int B_STAGE = 256 * BS;

    extern __shared__ float sm[];
    float* sA = sm;                       // [2][128][AS]
    float* sB = sm + 2 * A_STAGE;         // [2][256][72]

    const int tid  = threadIdx.x;
    const int wid  = tid >> 5;
    const int lane = tid & 31;
    const int g    = lane >> 2;      // 0..7
    const int t    = lane & 3;       // 0..3
    const int wm   = wid >> 2;       // 0..1
    const int wn   = wid & 3;        // 0..3
    const int m0   = blockIdx.x * 128;
    const int n0   = blockIdx.y * 256;

    const long long koff = (long long)blockIdx.z * Kps;
    A += koff;
    B += koff;
    C += (long long)blockIdx.z * c_zstride;

    // ---- tile loader: A 8 f4/thread, B 16 f4/thread ----
    auto load_tiles = [&](int c, int s) {
        const float* Ab = A + (size_t)m0 * lda + (size_t)c * BK;
        const float* Bb = B + (size_t)c * BK;
        const uint32_t sAa = smem_u32(sA + s * A_STAGE);
        const uint32_t sBa = smem_u32(sB + s * B_STAGE);
        #pragma unroll
        for (int q = 0; q < 8; ++q) {                // A: 128 rows x 16 f4
            int idx = tid + q * 256;
            int r = idx >> 4, j = idx & 15;
            const float* gp = Ab + (size_t)r * lda + j * 4;
            uint32_t da = sAa + (uint32_t)(r * AS + j * 4) * 4;
            asm volatile("cp.async.cg.shared.global [%0], [%1], 16;"
                         :: "r"(da), "l"(gp) : "memory");
        }
        #pragma unroll
        for (int q = 0; q < 16; ++q) {               // B: 256 rows x 16 f4
            int idx = tid + q * 256;
            int r = idx >> 4, j = idx & 15;
            int gn = n0 + r;
            int ok = (gn < nvalidB);
            const float* gq = Bb + (size_t)(ok ? gn : 0) * ldb + j * 4;
            uint32_t db = sBa + (uint32_t)(r * BS + j * 4) * 4;
            int sz = ok ? 16 : 0;
            asm volatile("cp.async.cg.shared.global [%0], [%1], 16, %2;"
                         :: "r"(db), "l"(gq), "r"(sz) : "memory");
        }
        asm volatile("cp.async.commit_group;" ::: "memory");
    };

    float acc[4][8][4];
    #pragma unroll
    for (int i = 0; i < 4; ++i)
        #pragma unroll
        for (int j = 0; j < 8; ++j)
            #pragma unroll
            for (int k = 0; k < 4; ++k) acc[i][j][k] = 0.f;

    const int NCH = Kps / BK;
    load_tiles(0, 0);

    for (int c = 0; c < NCH; ++c) {
        if (c + 1 < NCH) {
            load_tiles(c + 1, (c + 1) & 1);
            asm volatile("cp.async.wait_group 1;" ::: "memory");
        } else {
            asm volatile("cp.async.wait_group 0;" ::: "memory");
        }
        __syncthreads();

        const int s = c & 1;
        const uint32_t* tA = reinterpret_cast<const uint32_t*>(sA + s * A_STAGE);
        const uint32_t* tB = reinterpret_cast<const uint32_t*>(sB + s * B_STAGE);

        #pragma unroll
        for (int ks = 0; ks < 8; ++ks) {
            const int kb = ks * 8;
            uint2 bf[8];
            #pragma unroll
            for (int ni = 0; ni < 8; ++ni) {
                int col = wn * 64 + ni * 8 + g;
                bf[ni] = *reinterpret_cast<const uint2*>(tB + col * BS + kb + 2 * t);
            }
            #pragma unroll
            for (int mi = 0; mi < 4; ++mi) {
                int rr = wm * 64 + mi * 16 + g;
                uint32_t a0, a1, a2, a3;
                if (APERM) {
                    uint2 qa = *reinterpret_cast<const uint2*>(tA + rr * AS + kb + 2 * t);
                    uint2 qb = *reinterpret_cast<const uint2*>(tA + (rr + 8) * AS + kb + 2 * t);
                    a0 = qa.x; a2 = qa.y; a1 = qb.x; a3 = qb.y;
                } else {
                    a0 = tA[rr * AS + kb + t];
                    a2 = tA[rr * AS + kb + t + 4];
                    a1 = tA[(rr + 8) * AS + kb + t];
                    a3 = tA[(rr + 8) * AS + kb + t + 4];
                }
                #pragma unroll
                for (int ni = 0; ni < 8; ++ni)
                    mma_tf32(acc[mi][ni], a0, a1, a2, a3, bf[ni].x, bf[ni].y);
            }
        }
        __syncthreads();
    }

    // ---- epilogue: natural coalesced float2 stores ----
    #pragma unroll
    for (int mi = 0; mi < 4; ++mi) {
        const int rr = m0 + wm * 64 + mi * 16 + g;
        #pragma unroll
        for (int ni = 0; ni < 8; ++ni) {
            const int col = n0 + wn * 64 + ni * 8 + 2 * t;
            float v0 = acc[mi][ni][0], v1 = acc[mi][ni][1];
            float v2 = acc[mi][ni][2], v3 = acc[mi][ni][3];
            if (epi_mode == 0) {
                float b0 = (col     < nvalidB) ? aux[col]     : 0.f;
                float b1 = (col + 1 < nvalidB) ? aux[col + 1] : 0.f;
                v0 += b0; v1 += b1; v2 += b0; v3 += b1;
                if (col     >= nvalidB) { v0 = -1e30f; v2 = -1e30f; }
                if (col + 1 >= nvalidB) { v1 = -1e30f; v3 = -1e30f; }
            } else if (epi_mode == 2) {
                float b0 = aux[col], b1 = aux[col + 1];
                v0 += b0; v1 += b1; v2 += b0; v3 += b1;
            }
            *reinterpret_cast<float2*>(C + (size_t)rr * ldc + col) =
                make_float2(v0, v1);
            *reinterpret_cast<float2*>(C + (size_t)(rr + 8) * ldc + col) =
                make_float2(v2, v3);
        }
    }
}

// ============================================================================
// prep: rounded + perm8 copy. Each thread handles 8 consecutive floats.
// ============================================================================
__global__ void __launch_bounds__(256)
round_copy_perm(const float* __restrict__ in, float* __restrict__ out,
                long long n)
{
    long long i8 = ((long long)blockIdx.x * 256 + threadIdx.x) * 8;
    if (i8 >= n) return;
    float4 u = *reinterpret_cast<const float4*>(in + i8);
    float4 v = *reinterpret_cast<const float4*>(in + i8 + 4);
    float4 o0 = make_float4(tf32r(u.x), tf32r(v.x), tf32r(u.y), tf32r(v.y));
    float4 o1 = make_float4(tf32r(u.z), tf32r(v.z), tf32r(u.w), tf32r(v.w));
    *reinterpret_cast<float4*>(out + i8)     = o0;
    *reinterpret_cast<float4*>(out + i8 + 4) = o1;
}

// ============================================================================
// WvT[d, perm(v)] = round(Wv[v, d])  (padded to VPAD with zeros)
// ============================================================================
__global__ void __launch_bounds__(256)
transpose_wv(const float* __restrict__ Wv, float* __restrict__ WvT)
{
    __shared__ float tt[32][33];
    const int v0 = blockIdx.x * 32;
    const int d0 = blockIdx.y * 32;
    const int tx = threadIdx.x & 31;
    const int ty = threadIdx.x >> 5;     // 0..7
    #pragma unroll
    for (int i = 0; i < 32; i += 8) {
        int v = v0 + ty + i;
        tt[ty + i][tx] = (v < VOCAB) ? tf32r(Wv[(size_t)v * DDIM + d0 + tx]) : 0.f;
    }
    __syncthreads();
    const int pcol = v0 + (tx & 24) + pos8(tx & 7);
    #pragma unroll
    for (int i = 0; i < 32; i += 8)
        WvT[(size_t)(d0 + ty + i) * VPAD + pcol] = tt[tx][ty + i];
}

// ============================================================================
// Row softmax: online (m,l), p = round(exp(x-m)/l) in place (natural layout).
// ============================================================================
__global__ void __launch_bounds__(256)
softmax_rows(float* __restrict__ L)
{
    __shared__ float sm_m[256], sm_s[256];
    const int row = blockIdx.x;
    float* rp = L + (size_t)row * VPAD;
    const int tid = threadIdx.x;

    float m = -3.0e38f, s = 0.f;
    for (int i = tid; i < VPAD / 4; i += 256) {
        float4 v = reinterpret_cast<const float4*>(rp)[i];
        float xs[4] = {v.x, v.y, v.z, v.w};
        #pragma unroll
        for (int q = 0; q < 4; ++q) {
            float x = xs[q];
            if (x > m) { s = s * __expf(m - x) + 1.f; m = x; }
            else       { s += __expf(x - m); }
        }
    }
    sm_m[tid] = m; sm_s[tid] = s;
    __syncthreads();
    for (int off = 128; off > 0; off >>= 1) {
        if (tid < off) {
            float m2 = sm_m[tid + off], s2 = sm_s[tid + off];
            float m1 = sm_m[tid],       s1 = sm_s[tid];
            float M = fmaxf(m1, m2);
            sm_s[tid] = s1 * __expf(m1 - M) + s2 * __expf(m2 - M);
            sm_m[tid] = M;
        }
        __syncthreads();
    }
    const float M = sm_m[0];
    const float R = 1.0f / sm_s[0];

    for (int i = tid; i < VPAD / 4; i += 256) {
        float4 v = reinterpret_cast<const float4*>(rp)[i];
        v.x = tf32r(__expf(v.x - M) * R);
        v.y = tf32r(__expf(v.y - M) * R);
        v.z = tf32r(__expf(v.z - M) * R);
        v.w = tf32r(__expf(v.w - M) * R);
        reinterpret_cast<float4*>(rp)[i] = v;
    }
}

// ============================================================================
// split-K reduction: h = round(sum_z hp[z])   (natural layout)
// ============================================================================
__global__ void __launch_bounds__(256)
reduce_splitk(const float* __restrict__ hp, float* __restrict__ h)
{
    const size_t MD = (size_t)MROWS * DDIM;
    size_t i = ((size_t)blockIdx.x * 256 + threadIdx.x) * 4;
    float4 u = *reinterpret_cast<const float4*>(hp + i);
    #pragma unroll
    for (int z = 1; z < SPLITK; ++z) {
        float4 b = *reinterpret_cast<const float4*>(hp + z * MD + i);
        u.x += b.x; u.y += b.y; u.z += b.z; u.w += b.w;
    }
    u.x = tf32r(u.x); u.y = tf32r(u.y); u.z = tf32r(u.z); u.w = tf32r(u.w);
    *reinterpret_cast<float4*>(h + i) = u;
}

// ============================================================================
// host launcher
// ============================================================================
extern "C" void kernel_launch(void* const* d_in, const int* in_sizes, int n_in,
                              void* d_out, int out_size)
{
    const float* x  = (const float*)d_in[0];
    const float* Wv = (const float*)d_in[1];
    const float* bv = (const float*)d_in[2];
    const float* Wl = (const float*)d_in[3];
    const float* bl = (const float*)d_in[4];
    float* out = (float*)d_out;

    void *p_probs, *p_wvt, *p_wvr, *p_xr, *p_wlr, *p_hp, *p_h;
    cudaGetSymbolAddress(&p_probs, g_probs);
    cudaGetSymbolAddress(&p_wvt,   g_wvt);
    cudaGetSymbolAddress(&p_wvr,   g_wvr);
    cudaGetSymbolAddress(&p_xr,    g_xr);
    cudaGetSymbolAddress(&p_wlr,   g_wlr);
    cudaGetSymbolAddress(&p_hp,    g_hp);
    cudaGetSymbolAddress(&p_h,     g_h);
    float* probs = (float*)p_probs;
    float* wvt   = (float*)p_wvt;
    float* wvr   = (float*)p_wvr;
    float* xr    = (float*)p_xr;
    float* wlr   = (float*)p_wlr;
    float* hp    = (float*)p_hp;
    float* h     = (float*)p_h;

    const int SMEM_P = 2 * (128 * 72 + 256 * 72) * 4;   // 221184 (APERM=true)
    const int SMEM_N = 2 * (128 * 68 + 256 * 72) * 4;   // 217088 (APERM=false)
    static bool attr_set = false;
    if (!attr_set) {
        cudaFuncSetAttribute(gemm_tn<true>,
            cudaFuncAttributeMaxDynamicSharedMemorySize, SMEM_P);
        cudaFuncSetAttribute(gemm_tn<false>,
            cudaFuncAttributeMaxDynamicSharedMemorySize, SMEM_N);
        attr_set = true;
    }

    // 1) prep: rounded + perm8 copies of x, Wl, Wv; perm transpose of Wv
    const long long nX = (long long)MROWS * DDIM;
    const long long nL = (long long)DDIM * DDIM;
    const long long nV = (long long)VOCAB * DDIM;
    round_copy_perm<<<(int)((nX / 8 + 255) / 256), 256>>>(x, xr, nX);
    round_copy_perm<<<(int)((nL / 8 + 255) / 256), 256>>>(Wl, wlr, nL);
    round_copy_perm<<<(int)((nV / 8 + 255) / 256), 256>>>(Wv, wvr, nV);
    transpose_wv<<<dim3(VPAD / 32, DDIM / 32), 256>>>(Wv, wvt);

    // 2) logits = xr @ wvr^T + bv  (natural coalesced stores)
    gemm_tn<true><<<dim3(MROWS / 128, VPAD / 256, 1), 256, SMEM_P>>>(
        xr, DDIM, wvr, DDIM, probs, VPAD, 0, DDIM, VOCAB, bv, 0);

    // 3) softmax in place
    softmax_rows<<<MROWS, 256>>>(probs);

    // 4) hp[z] = p @ wvt^T (split-K), then h = round(sum)
    gemm_tn<false><<<dim3(MROWS / 128, DDIM / 256, SPLITK), 256, SMEM_N>>>(
        probs, VPAD, wvt, VPAD, hp, DDIM, (long long)MROWS * DDIM,
        KSPLIT, DDIM, nullptr, 3);
    reduce_splitk<<<MROWS * DDIM / 1024, 256>>>(hp, h);

    // 5) out = h @ wlr^T + bl
    gemm_tn<false><<<dim3(MROWS / 128, DDIM / 256, 1), 256, SMEM_N>>>(
        h, DDIM, wlr, DDIM, out, DDIM, 0, DDIM, DDIM, bl, 2);
}